// round 8
// baseline (speedup 1.0000x reference)
#include <cuda_runtime.h>

// RandFlow: depthwise 41x41 Gaussian (sigma=5) of flow = 2*noise-1, separable.
// R8 = R7 kernels (unchanged math) + batch-chunked two-stream pipelining:
// pass1(chunk c) -> event -> pass2(chunk c) on a forked stream, so pass2 of
// chunk c overlaps pass1 of chunk c+1 (each kernel alone leaves ~46% of the
// FMA pipe idle; overlap reclaims it).

#define IMG_H 512
#define IMG_W 512
#define IMG_B 16
#define NCHUNK 4
#define BPC (IMG_B / NCHUNK)   // batches per chunk

__device__ unsigned long long g_scratch[IMG_B * IMG_H * IMG_W]; // float2 as u64

__device__ constexpr float GK[41] = {
    0.00033546f, 0.00073182f, 0.00153381f, 0.00308872f, 0.00597603f,
    0.01110900f, 0.01984110f, 0.03404746f, 0.05613476f, 0.08892166f,
    0.13533528f, 0.19789871f, 0.27803730f, 0.37531110f, 0.48675226f,
    0.60653066f, 0.72614904f, 0.83527021f, 0.92311635f, 0.98019867f,
    1.00000000f,
    0.98019867f, 0.92311635f, 0.83527021f, 0.72614904f, 0.60653066f,
    0.48675226f, 0.37531110f, 0.27803730f, 0.19789871f, 0.13533528f,
    0.08892166f, 0.05613476f, 0.03404746f, 0.01984110f, 0.01110900f,
    0.00597603f, 0.00308872f, 0.00153381f, 0.00073182f, 0.00033546f
};

// fold 1/S^2 (S = 12.5326388) and (2x-1) into pass-1 load
#define SCALE_A 0.012733434f
#define SCALE_B (-0.006366717f)

__device__ __forceinline__ unsigned long long pk2(float g) {
    unsigned int u = __float_as_uint(g);   // constant-folds for literals
    return ((unsigned long long)u << 32) | (unsigned long long)u;
}
__device__ __forceinline__ void ffma2(unsigned long long& d,
                                      unsigned long long a,
                                      unsigned long long b) {
    asm("fma.rn.f32x2 %0, %1, %2, %0;" : "+l"(d) : "l"(a), "l"(b));
}

// skew: f(x) = x + (x>>3)
#define SKB 624   // f(551)=619, padded

// ---------------- Pass 1: horizontal, 8 out/thread, ring W1=12 -------------
// 64 threads per row, 2 rows per block. Chunk grid = BPC*512/2 = 1024.
#define W1 12
__global__ void __launch_bounds__(128) rf_pass1(const float2* __restrict__ in,
                                                int b0) {
    __shared__ unsigned long long s[2][SKB];
    const int half = threadIdx.x >> 6;
    const int t    = threadIdx.x & 63;
    const int row  = b0 * IMG_H + blockIdx.x * 2 + half;  // global b*512 + h
    const float2* src = in + (size_t)row * IMG_W;
    unsigned long long* S = s[half];

    for (int x = t; x < IMG_W + 40; x += 64) {
        float vx = 0.f, vy = 0.f;
        int w = x - 20;
        if ((unsigned)w < (unsigned)IMG_W) {
            float2 v = src[w];
            vx = fmaf(v.x, SCALE_A, SCALE_B);
            vy = fmaf(v.y, SCALE_A, SCALE_B);
        }
        *reinterpret_cast<float2*>(&S[x + (x >> 3)]) = make_float2(vx, vy);
    }
    __syncthreads();

    const int base = t * 9;                    // skewed base (w0 = 8t)
    unsigned long long win[W1], acc[8];
#pragma unroll
    for (int i = 0; i < W1; ++i) win[i] = S[base + i + (i >> 3)];
#pragma unroll
    for (int r = 0; r < 8; ++r) acc[r] = 0ull;

#pragma unroll
    for (int k = 0; k < 41; ++k) {
        const unsigned long long g = pk2(GK[k]);
#pragma unroll
        for (int r = 0; r < 8; ++r) ffma2(acc[r], win[(k + r) % W1], g);
        if (k < 37) {
            const int i = k + W1;
            win[k % W1] = S[base + i + (i >> 3)];
        }
    }
    __syncthreads();

#pragma unroll
    for (int r = 0; r < 8; ++r) S[base + r] = acc[r];
    __syncthreads();

    unsigned long long* dst = g_scratch + (size_t)row * IMG_W;
#pragma unroll
    for (int j = 0; j < 8; ++j) {
        const int x = t + 64 * j;
        dst[x] = S[x + (x >> 3)];
    }
}

// ---------------- Pass 2: vertical, 16 out/thread, ring W2=24 --------------
// Chunk grid = BPC*(512/16)*4 = 512.
#define W2 24
__global__ void __launch_bounds__(128, 5) rf_pass2(float2* __restrict__ out,
                                                   int b0) {
    const int w  = (blockIdx.x & 3) * 128 + threadIdx.x;
    const int bh = blockIdx.x >> 2;
    const int b  = b0 + (bh >> 5);
    const int h0 = (bh & 31) * 16;

    const unsigned long long* src =
        g_scratch + (size_t)b * IMG_H * IMG_W + w;

    unsigned long long win[W2], acc[16];
#pragma unroll
    for (int i = 0; i < W2; ++i) {
        const int h = h0 + i - 20;
        win[i] = ((unsigned)h < (unsigned)IMG_H) ? src[(size_t)h * IMG_W] : 0ull;
    }
#pragma unroll
    for (int r = 0; r < 16; ++r) acc[r] = 0ull;

#pragma unroll
    for (int k = 0; k < 41; ++k) {
        const unsigned long long g = pk2(GK[k]);
#pragma unroll
        for (int r = 0; r < 16; ++r) ffma2(acc[r], win[(k + r) % W2], g);
        if (k < 32) {
            const int h = h0 + k + 4;
            win[k % W2] = ((unsigned)h < (unsigned)IMG_H) ? src[(size_t)h * IMG_W]
                                                          : 0ull;
        }
    }

    unsigned long long* dst = (unsigned long long*)out
                            + ((size_t)b * IMG_H + h0) * IMG_W + w;
#pragma unroll
    for (int r = 0; r < 16; ++r) dst[(size_t)r * IMG_W] = acc[r];
}

extern "C" void kernel_launch(void* const* d_in, const int* in_sizes, int n_in,
                              void* d_out, int out_size) {
    const float2* noise = nullptr;
    for (int i = 0; i < n_in; ++i) {
        if (in_sizes[i] == IMG_B * IMG_H * IMG_W * 2) {
            noise = (const float2*)d_in[i];
            break;
        }
    }
    if (!noise) noise = (const float2*)d_in[n_in - 1];
    float2* out = (float2*)d_out;

    // Fork/join pipeline: pass1 chunks chained on the launch stream; each
    // pass2 chunk on s2 gated by an event after its pass1 chunk. Host-side
    // creations happen only on real invocations (graph replay skips this).
    cudaStream_t s2;
    cudaStreamCreateWithFlags(&s2, cudaStreamNonBlocking);
    cudaEvent_t ev[NCHUNK], done;
    for (int c = 0; c < NCHUNK; ++c)
        cudaEventCreateWithFlags(&ev[c], cudaEventDisableTiming);
    cudaEventCreateWithFlags(&done, cudaEventDisableTiming);

    const int g1 = BPC * IMG_H / 2;                 // 1024
    const int g2 = BPC * (IMG_H / 16) * (IMG_W / 128);  // 512

    for (int c = 0; c < NCHUNK; ++c) {
        rf_pass1<<<g1, 128>>>(noise, c * BPC);
        cudaEventRecord(ev[c], 0);
        cudaStreamWaitEvent(s2, ev[c], 0);
        rf_pass2<<<g2, 128, 0, s2>>>(out, c * BPC);
    }
    cudaEventRecord(done, s2);
    cudaStreamWaitEvent(0, done, 0);   // join fork back into launch stream
}

// round 9
// speedup vs baseline: 2.0401x; 2.0401x over previous
#include <cuda_runtime.h>

// RandFlow: depthwise 41x41 Gaussian (sigma=5) of flow = 2*noise-1, separable.
// R9 = R7 + pass1 fill rework: predicate-free interior fill (8 unconditional
// coalesced LDG.64 per thread, MLP=8), separate edge-zeroing; 4 rows per
// 256-thread block. Pass2 unchanged (best known).

#define IMG_H 512
#define IMG_W 512
#define IMG_B 16

__device__ unsigned long long g_scratch[IMG_B * IMG_H * IMG_W]; // float2 as u64

__device__ constexpr float GK[41] = {
    0.00033546f, 0.00073182f, 0.00153381f, 0.00308872f, 0.00597603f,
    0.01110900f, 0.01984110f, 0.03404746f, 0.05613476f, 0.08892166f,
    0.13533528f, 0.19789871f, 0.27803730f, 0.37531110f, 0.48675226f,
    0.60653066f, 0.72614904f, 0.83527021f, 0.92311635f, 0.98019867f,
    1.00000000f,
    0.98019867f, 0.92311635f, 0.83527021f, 0.72614904f, 0.60653066f,
    0.48675226f, 0.37531110f, 0.27803730f, 0.19789871f, 0.13533528f,
    0.08892166f, 0.05613476f, 0.03404746f, 0.01984110f, 0.01110900f,
    0.00597603f, 0.00308872f, 0.00153381f, 0.00073182f, 0.00033546f
};

// fold 1/S^2 (S = 12.5326388) and (2x-1) into pass-1 load
#define SCALE_A 0.012733434f
#define SCALE_B (-0.006366717f)

__device__ __forceinline__ unsigned long long pk2(float g) {
    unsigned int u = __float_as_uint(g);   // constant-folds for literals
    return ((unsigned long long)u << 32) | (unsigned long long)u;
}
__device__ __forceinline__ void ffma2(unsigned long long& d,
                                      unsigned long long a,
                                      unsigned long long b) {
    asm("fma.rn.f32x2 %0, %1, %2, %0;" : "+l"(d) : "l"(a), "l"(b));
}

// skew: f(x) = x + (x>>3)
#define SKB 624   // f(551)=619, padded

// ---------------- Pass 1: horizontal, 8 out/thread, ring W1=12 -------------
// 256 threads = 4 rows x 64 threads. Grid = 16*512/4 = 2048.
#define W1 12
__global__ void __launch_bounds__(256) rf_pass1(const float2* __restrict__ in) {
    __shared__ unsigned long long s[4][SKB];
    const int sub  = threadIdx.x >> 6;         // row within block (0..3)
    const int t    = threadIdx.x & 63;         // thread within row
    const int row  = blockIdx.x * 4 + sub;     // b*512 + h
    const float2* src = in + (size_t)row * IMG_W;
    unsigned long long* S = s[sub];

    // interior fill: x = 20 + t + 64j  ->  w = t + 64j in [0,512), no predicate
    {
        float2 v[8];
#pragma unroll
        for (int j = 0; j < 8; ++j) v[j] = src[t + 64 * j];   // MLP = 8
#pragma unroll
        for (int j = 0; j < 8; ++j) {
            const int x = 20 + t + 64 * j;
            float vx = fmaf(v[j].x, SCALE_A, SCALE_B);
            float vy = fmaf(v[j].y, SCALE_A, SCALE_B);
            *reinterpret_cast<float2*>(&S[x + (x >> 3)]) = make_float2(vx, vy);
        }
        // edges: x in [0,20) and [532,552) are zero padding
        if (t < 20) {
            S[t + (t >> 3)] = 0ull;
            const int x = 532 + t;
            S[x + (x >> 3)] = 0ull;
        }
    }
    __syncthreads();

    const int base = t * 9;                    // skewed base (w0 = 8t)
    unsigned long long win[W1], acc[8];
#pragma unroll
    for (int i = 0; i < W1; ++i) win[i] = S[base + i + (i >> 3)];
#pragma unroll
    for (int r = 0; r < 8; ++r) acc[r] = 0ull;

#pragma unroll
    for (int k = 0; k < 41; ++k) {
        const unsigned long long g = pk2(GK[k]);
#pragma unroll
        for (int r = 0; r < 8; ++r) ffma2(acc[r], win[(k + r) % W1], g);
        if (k < 37) {                          // prefetch i = k + 12 (max 48)
            const int i = k + W1;
            win[k % W1] = S[base + i + (i >> 3)];
        }
    }
    __syncthreads();

    // stage outputs at skewed f(8t+r) = 9t + r, then coalesced stores
#pragma unroll
    for (int r = 0; r < 8; ++r) S[base + r] = acc[r];
    __syncthreads();

    unsigned long long* dst = g_scratch + (size_t)row * IMG_W;
#pragma unroll
    for (int j = 0; j < 8; ++j) {
        const int x = t + 64 * j;
        dst[x] = S[x + (x >> 3)];
    }
}

// ---------------- Pass 2: vertical, 16 out/thread, ring W2=24 --------------
#define W2 24
__global__ void __launch_bounds__(128, 5) rf_pass2(float2* __restrict__ out) {
    const int w  = (blockIdx.x & 3) * 128 + threadIdx.x;
    const int bh = blockIdx.x >> 2;
    const int b  = bh >> 5;
    const int h0 = (bh & 31) * 16;

    const unsigned long long* src =
        g_scratch + (size_t)b * IMG_H * IMG_W + w;

    unsigned long long win[W2], acc[16];
#pragma unroll
    for (int i = 0; i < W2; ++i) {
        const int h = h0 + i - 20;
        win[i] = ((unsigned)h < (unsigned)IMG_H) ? src[(size_t)h * IMG_W] : 0ull;
    }
#pragma unroll
    for (int r = 0; r < 16; ++r) acc[r] = 0ull;

#pragma unroll
    for (int k = 0; k < 41; ++k) {
        const unsigned long long g = pk2(GK[k]);
#pragma unroll
        for (int r = 0; r < 16; ++r) ffma2(acc[r], win[(k + r) % W2], g);
        if (k < 32) {                          // prefetch i = k + 24
            const int h = h0 + k + 4;
            win[k % W2] = ((unsigned)h < (unsigned)IMG_H) ? src[(size_t)h * IMG_W]
                                                          : 0ull;
        }
    }

    unsigned long long* dst = (unsigned long long*)out
                            + ((size_t)b * IMG_H + h0) * IMG_W + w;
#pragma unroll
    for (int r = 0; r < 16; ++r) dst[(size_t)r * IMG_W] = acc[r];
}

extern "C" void kernel_launch(void* const* d_in, const int* in_sizes, int n_in,
                              void* d_out, int out_size) {
    const float2* noise = nullptr;
    for (int i = 0; i < n_in; ++i) {
        if (in_sizes[i] == IMG_B * IMG_H * IMG_W * 2) {
            noise = (const float2*)d_in[i];
            break;
        }
    }
    if (!noise) noise = (const float2*)d_in[n_in - 1];

    rf_pass1<<<IMG_B * IMG_H / 4, 256>>>(noise);
    rf_pass2<<<IMG_B * (IMG_H / 16) * (IMG_W / 128), 128>>>((float2*)d_out);
}